// round 3
// baseline (speedup 1.0000x reference)
#include <cuda_runtime.h>

#define BB 8
#define LL 512
#define DD 128
#define INV_SCALE 0.08838834764831843f   // 1/sqrt(128)

// ---- scratch (no cudaMalloc allowed) ----
__device__ float g_Q[BB*LL*DD];
__device__ float g_K[BB*LL*DD];
__device__ float g_V[BB*LL*DD];

__device__ __forceinline__ float fast_tanh(float x) {
    float y;
    asm("tanh.approx.f32 %0, %1;" : "=f"(y) : "f"(x));
    return y;
}

// =====================================================================
// Projection: out = X @ W.T + b   (X: [4096,128], W: [128,128] (out,in))
// grid 96 (mat = bx/32, 128-row tile = bx%32), 256 threads
// smem: Xs[128][129] + Wt[128][129] (Wt[d][c]) = 132096 B dynamic
// =====================================================================
__global__ void __launch_bounds__(256) proj_kernel(
    const float* __restrict__ Xq, const float* __restrict__ Xk, const float* __restrict__ Xv,
    const float* __restrict__ Wq, const float* __restrict__ bq,
    const float* __restrict__ Wk, const float* __restrict__ bk,
    const float* __restrict__ Wv, const float* __restrict__ bv)
{
    extern __shared__ float sm[];
    float* Xs = sm;               // [128][129]
    float* Wt = sm + 128*129;     // [128][129]  Wt[d][c]
    __shared__ float bs[DD];

    int bx  = blockIdx.x;
    int mat = bx >> 5;
    int rt  = bx & 31;
    const float *X, *W, *bias;
    float* out;
    if (mat == 0)      { X = Xq; W = Wq; bias = bq; out = g_Q; }
    else if (mat == 1) { X = Xk; W = Wk; bias = bk; out = g_K; }
    else               { X = Xv; W = Wv; bias = bv; out = g_V; }

    int tid = threadIdx.x;
    const float4* Xg = (const float4*)(X + rt*128*DD);
    const float4* Wg = (const float4*)W;
    #pragma unroll
    for (int it = 0; it < 16; ++it) {
        int idx = it*256 + tid;           // 0..4095 float4 groups
        int d4  = idx & 31;               // d = 4*d4
        int r   = idx >> 5;               // row (or col c for W)
        float4 xv = Xg[idx];
        float* xd = Xs + r*129 + 4*d4;
        xd[0] = xv.x; xd[1] = xv.y; xd[2] = xv.z; xd[3] = xv.w;
        float4 wv = Wg[idx];
        Wt[(4*d4+0)*129 + r] = wv.x;
        Wt[(4*d4+1)*129 + r] = wv.y;
        Wt[(4*d4+2)*129 + r] = wv.z;
        Wt[(4*d4+3)*129 + r] = wv.w;
    }
    if (tid < DD) bs[tid] = bias[tid];
    __syncthreads();

    int tr = tid >> 4;     // 0..15 (8-row group)
    int tc = tid & 15;     // 0..15 (8-col group)
    const float* xb = Xs + (tr*8)*129;
    const float* wb = Wt + tc*8;

    float acc[8][8];
    #pragma unroll
    for (int i = 0; i < 8; ++i)
        #pragma unroll
        for (int j = 0; j < 8; ++j) acc[i][j] = 0.f;

    #pragma unroll 4
    for (int d = 0; d < DD; ++d) {
        float xs[8], ws[8];
        #pragma unroll
        for (int i = 0; i < 8; ++i) xs[i] = xb[i*129 + d];
        #pragma unroll
        for (int j = 0; j < 8; ++j) ws[j] = wb[d*129 + j];
        #pragma unroll
        for (int i = 0; i < 8; ++i)
            #pragma unroll
            for (int j = 0; j < 8; ++j) acc[i][j] += xs[i] * ws[j];
    }

    int rbase = rt*128 + tr*8;
    #pragma unroll
    for (int i = 0; i < 8; ++i) {
        float* orow = out + (rbase + i)*DD + tc*8;
        #pragma unroll
        for (int j = 0; j < 8; ++j) orow[j] = acc[i][j] + bs[tc*8 + j];
    }
}

// =====================================================================
// Attention: per block = one batch b, one 32-row q tile. 512 threads.
// Phase 1: scores S[32][512] = sum_d tanh(Q+K)*w_all  (MUFU-bound)
// Phase 2: row softmax (unnormalized exp + 1/sum)
// Phase 3: O = P @ V (FMA-bound), scaled by 1/sum at epilogue
// smem: Qs[32][128] | S[32][512] | KV (Kt[128][65] / Vs[64][128]) | w[128] | rinv[32]
// =====================================================================
#define SM_QS   0
#define SM_S    (32*128)
#define SM_KV   (SM_S + 32*512)
#define SM_W    (SM_KV + 128*65)
#define SM_RINV (SM_W + 128)
#define ATTN_SMEM_FLOATS (SM_RINV + 32)

__global__ void __launch_bounds__(512) attn_kernel(
    const float* __restrict__ wdel, const float* __restrict__ wsig,
    const float* __restrict__ wthe, float* __restrict__ out)
{
    extern __shared__ float sm[];
    float* Qs   = sm + SM_QS;
    float* S    = sm + SM_S;
    float* KV   = sm + SM_KV;
    float* wsh  = sm + SM_W;
    float* rinv = sm + SM_RINV;

    int tid  = threadIdx.x;
    int w    = tid >> 5;
    int lane = tid & 31;
    int b    = blockIdx.x >> 4;
    int qt   = blockIdx.x & 15;
    int qbase = qt * 32;

    const float* Qg = g_Q + (b*LL + qbase)*DD;
    const float* Kg = g_K + b*LL*DD;
    const float* Vg = g_V + b*LL*DD;

    // stage Q tile (linear) + combined weight vector
    {
        const float4* src = (const float4*)Qg;
        float4* dst = (float4*)Qs;
        #pragma unroll
        for (int i = 0; i < 2; ++i) dst[i*512 + tid] = src[i*512 + tid];
        if (tid < DD) wsh[tid] = INV_SCALE + wdel[tid] + wsig[tid] + wthe[tid];
    }

    // ---------------- Phase 1: scores ----------------
    int q0 = 2*w, q1 = q0 + 1;
    for (int kt = 0; kt < 8; ++kt) {
        __syncthreads();   // KV free (also covers Qs/wsh staging on first iter)
        // stage K tile transposed: Kt[d][k], pitch 65
        const float4* Ksrc = (const float4*)(Kg + kt*64*DD);
        #pragma unroll
        for (int it = 0; it < 4; ++it) {
            int idx = it*512 + tid;        // 0..2047
            int d4 = idx & 31, k = idx >> 5;
            float4 v = Ksrc[idx];
            KV[(4*d4+0)*65 + k] = v.x;
            KV[(4*d4+1)*65 + k] = v.y;
            KV[(4*d4+2)*65 + k] = v.z;
            KV[(4*d4+3)*65 + k] = v.w;
        }
        __syncthreads();

        float a00 = 0.f, a01 = 0.f, a10 = 0.f, a11 = 0.f;
        #pragma unroll 4
        for (int d = 0; d < DD; ++d) {
            float kv0 = KV[d*65 + lane];
            float kv1 = KV[d*65 + 32 + lane];
            float qv0 = Qs[q0*128 + d];
            float qv1 = Qs[q1*128 + d];
            float wv  = wsh[d];
            a00 += fast_tanh(qv0 + kv0) * wv;
            a01 += fast_tanh(qv0 + kv1) * wv;
            a10 += fast_tanh(qv1 + kv0) * wv;
            a11 += fast_tanh(qv1 + kv1) * wv;
        }
        S[q0*512 + kt*64 + lane]      = a00;
        S[q0*512 + kt*64 + 32 + lane] = a01;
        S[q1*512 + kt*64 + lane]      = a10;
        S[q1*512 + kt*64 + 32 + lane] = a11;
    }
    // each warp softmaxes the rows it wrote itself -> no sync needed here

    // ---------------- Phase 2: softmax (b_all is softmax-invariant) ----------------
    #pragma unroll
    for (int rr = 0; rr < 2; ++rr) {
        int q = 2*w + rr;
        float* Srow = S + q*512;
        float v[16];
        float m = -1e30f;
        #pragma unroll
        for (int i = 0; i < 16; ++i) { v[i] = Srow[i*32 + lane]; m = fmaxf(m, v[i]); }
        #pragma unroll
        for (int s = 16; s > 0; s >>= 1) m = fmaxf(m, __shfl_xor_sync(0xffffffffu, m, s));
        float sum = 0.f;
        #pragma unroll
        for (int i = 0; i < 16; ++i) {
            float e = __expf(v[i] - m);
            Srow[i*32 + lane] = e;
            sum += e;
        }
        #pragma unroll
        for (int s = 16; s > 0; s >>= 1) sum += __shfl_xor_sync(0xffffffffu, sum, s);
        if (lane == 0) rinv[q] = 1.0f / sum;
    }
    __syncthreads();

    // ---------------- Phase 3: O = P @ V ----------------
    // warp -> 4 rows (rg = w&7) x 64-col half (dh = w>>3); lane covers 2 floats
    int rg = w & 7, dh = w >> 3;
    int r0 = rg * 4;
    int dof = dh*64 + 2*lane;
    float acc[4][2] = {{0.f,0.f},{0.f,0.f},{0.f,0.f},{0.f,0.f}};

    for (int kt = 0; kt < 8; ++kt) {
        __syncthreads();   // previous V tile consumed
        const float4* Vsrc = (const float4*)(Vg + kt*64*DD);
        float4* Vdst = (float4*)KV;        // Vs[64][128] linear
        #pragma unroll
        for (int it = 0; it < 4; ++it) Vdst[it*512 + tid] = Vsrc[it*512 + tid];
        __syncthreads();

        #pragma unroll 4
        for (int k = 0; k < 64; k += 4) {
            float4 P0 = *(const float4*)(S + (r0+0)*512 + kt*64 + k);
            float4 P1 = *(const float4*)(S + (r0+1)*512 + kt*64 + k);
            float4 P2 = *(const float4*)(S + (r0+2)*512 + kt*64 + k);
            float4 P3 = *(const float4*)(S + (r0+3)*512 + kt*64 + k);
            float p0[4] = {P0.x, P0.y, P0.z, P0.w};
            float p1[4] = {P1.x, P1.y, P1.z, P1.w};
            float p2[4] = {P2.x, P2.y, P2.z, P2.w};
            float p3[4] = {P3.x, P3.y, P3.z, P3.w};
            #pragma unroll
            for (int m = 0; m < 4; ++m) {
                float2 vv = *(const float2*)(KV + (k+m)*128 + dof);
                acc[0][0] += p0[m]*vv.x;  acc[0][1] += p0[m]*vv.y;
                acc[1][0] += p1[m]*vv.x;  acc[1][1] += p1[m]*vv.y;
                acc[2][0] += p2[m]*vv.x;  acc[2][1] += p2[m]*vv.y;
                acc[3][0] += p3[m]*vv.x;  acc[3][1] += p3[m]*vv.y;
            }
        }
    }

    #pragma unroll
    for (int i = 0; i < 4; ++i) {
        float inv = rinv[r0 + i];
        float2 o;
        o.x = acc[i][0] * inv;
        o.y = acc[i][1] * inv;
        *(float2*)(out + (size_t)((b*LL + qbase + r0 + i))*DD + dof) = o;
    }
}

// =====================================================================
extern "C" void kernel_launch(void* const* d_in, const int* in_sizes, int n_in,
                              void* d_out, int out_size)
{
    const float* query = (const float*)d_in[0];
    const float* key   = (const float*)d_in[1];
    const float* value = (const float*)d_in[2];
    const float* Wq    = (const float*)d_in[3];
    const float* bq    = (const float*)d_in[4];
    const float* Wk    = (const float*)d_in[5];
    const float* bk    = (const float*)d_in[6];
    const float* Wv    = (const float*)d_in[7];
    const float* bv    = (const float*)d_in[8];
    const float* wdel  = (const float*)d_in[9];
    const float* wsig  = (const float*)d_in[11];
    const float* wthe  = (const float*)d_in[13];
    float* out = (float*)d_out;

    const int PROJ_SMEM = 2 * 128 * 129 * (int)sizeof(float);        // 132096
    const int ATTN_SMEM = ATTN_SMEM_FLOATS * (int)sizeof(float);     // 115840

    cudaFuncSetAttribute(proj_kernel, cudaFuncAttributeMaxDynamicSharedMemorySize, PROJ_SMEM);
    cudaFuncSetAttribute(attn_kernel, cudaFuncAttributeMaxDynamicSharedMemorySize, ATTN_SMEM);

    proj_kernel<<<96, 256, PROJ_SMEM>>>(query, key, value, Wq, bq, Wk, bk, Wv, bv);
    attn_kernel<<<BB*16, 512, ATTN_SMEM>>>(wdel, wsig, wthe, out);
}